// round 4
// baseline (speedup 1.0000x reference)
#include <cuda_runtime.h>
#include <math.h>
#include <stdint.h>

// Problem shape (fixed): B=512, L=512, D=256, fp32.
#define BATCH 512
#define LDIM  512
#define DDIM  256
#define EPSV  1e-6f

#define CTM 256              // CTA tile rows
#define CTN 128              // CTA tile cols
#define KCH 32               // K elements staged per chunk
#define NCHUNK (DDIM/KCH)    // 8
#define RS 40                // smem row stride in floats (conflict-free frag loads)

// smem (floats): As[2][256][RS] | Bs[2][128][RS] | r1[256] | r2[128]
#define ATILEF (256*RS)                 // 10240
#define BTILEF (128*RS)                 // 5120
#define AS_OFF(b) ((b)*ATILEF)
#define BS_OFF(b) (2*ATILEF + (b)*BTILEF)
#define R1_OFF   (2*ATILEF + 2*BTILEF)          // 30720
#define R2_OFF   (R1_OFF + 256)
#define SMEM_FLOATS (R2_OFF + 128)
#define SMEM_BYTES  (SMEM_FLOATS*4)             // 124,928 B

__device__ __forceinline__ uint32_t f2tf32(float x) {
    uint32_t r; asm("cvt.rna.tf32.f32 %0, %1;" : "=r"(r) : "f"(x)); return r;
}
__device__ __forceinline__ float fsqrt_fast(float x) {
    float y; asm("sqrt.approx.f32 %0, %1;" : "=f"(y) : "f"(x)); return y;
}
__device__ __forceinline__ void mma_tf32(float* c,
                                         uint32_t a0, uint32_t a1, uint32_t a2, uint32_t a3,
                                         uint32_t b0, uint32_t b1) {
    asm volatile(
        "mma.sync.aligned.m16n8k8.row.col.f32.tf32.tf32.f32 "
        "{%0,%1,%2,%3}, {%4,%5,%6,%7}, {%8,%9}, {%0,%1,%2,%3};"
        : "+f"(c[0]), "+f"(c[1]), "+f"(c[2]), "+f"(c[3])
        : "r"(a0), "r"(a1), "r"(a2), "r"(a3), "r"(b0), "r"(b1));
}

// ---------------------------------------------------------------------------
__global__ __launch_bounds__(256, 1)
void dist_tf32_kernel(const float* __restrict__ A, const float* __restrict__ B,
                      float* __restrict__ out) {
    extern __shared__ float smf[];

    const int tid = threadIdx.x;
    const int wid = tid >> 5, lid = tid & 31;
    const int b  = blockIdx.z;
    const int m0 = blockIdx.y * CTM;
    const int n0 = blockIdx.x * CTN;

    // ---- loader mapping ----
    // A: 1 thread per row (256 rows), 32 cols per chunk (8 float4)
    // B: 2 threads per row (128 rows), 16 cols each (4 float4)
    const int arow = tid;
    const int brow = tid >> 1;
    const int bh   = tid & 1;
    const float* Ap = A + ((size_t)(b * LDIM + m0 + arow)) * DDIM;
    const float* Bp = B + ((size_t)(b * LDIM + n0 + brow)) * DDIM;

    // ---- compute mapping: 4x2 warp grid, 64x64 warp tiles ----
    const int wm = wid >> 1;         // 0..3
    const int wn = wid & 1;          // 0..1
    const int g   = lid >> 2;        // 0..7
    const int tig = lid & 3;         // 0..3
    const int klane = 2 * tig;

    float acc[4][8][4];
#pragma unroll
    for (int mt = 0; mt < 4; mt++)
#pragma unroll
        for (int nt = 0; nt < 8; nt++)
#pragma unroll
            for (int r = 0; r < 4; r++) acc[mt][nt][r] = 0.f;

    float ssa = 0.f, sa = 0.f, ssb = 0.f, sB = 0.f;
    float4 av[8], bv[4];

    // ---- staging helpers (rotated stores, conflict-free per 8-lane phase) ----
    // A: group j' = (t + arow + 2*(arow>>3)) & 7 ; B: j' = (t + brow) & 3
    // ---- prologue: load + stage chunk 0 ----
#pragma unroll
    for (int j = 0; j < 8; j++) av[j] = *reinterpret_cast<const float4*>(Ap + 4 * j);
#pragma unroll
    for (int j = 0; j < 4; j++) bv[j] = *reinterpret_cast<const float4*>(Bp + bh * 16 + 4 * j);
    {
        const int arot = (arow + 2 * (arow >> 3)) & 7;
        const int brot = brow & 3;
#pragma unroll
        for (int t = 0; t < 8; t++) {
            int j = (t + arot) & 7;
            float4 a = av[j];
            ssa = fmaf(a.x, a.x, ssa); ssa = fmaf(a.y, a.y, ssa);
            ssa = fmaf(a.z, a.z, ssa); ssa = fmaf(a.w, a.w, ssa);
            sa += a.x + a.y + a.z + a.w;
            uint4 ua = make_uint4(f2tf32(a.x), f2tf32(a.y), f2tf32(a.z), f2tf32(a.w));
            *reinterpret_cast<uint4*>(&smf[AS_OFF(0) + arow * RS + 4 * j]) = ua;
        }
#pragma unroll
        for (int t = 0; t < 4; t++) {
            int j = (t + brot) & 3;
            float4 v = bv[j];
            ssb = fmaf(v.x, v.x, ssb); ssb = fmaf(v.y, v.y, ssb);
            ssb = fmaf(v.z, v.z, ssb); ssb = fmaf(v.w, v.w, ssb);
            sB += v.x + v.y + v.z + v.w;
            uint4 ub = make_uint4(f2tf32(v.x), f2tf32(v.y), f2tf32(v.z), f2tf32(v.w));
            *reinterpret_cast<uint4*>(&smf[BS_OFF(0) + brow * RS + bh * 16 + 4 * j]) = ub;
        }
    }
    __syncthreads();

    const int arow0 = wm * 64 + g;
    const int brow0 = wn * 64 + g;

#pragma unroll 1
    for (int kt = 0; kt < NCHUNK; kt++) {
        const int buf = kt & 1;

        if (kt + 1 < NCHUNK) {
            const int cb = (kt + 1) * KCH;
#pragma unroll
            for (int j = 0; j < 8; j++)
                av[j] = *reinterpret_cast<const float4*>(Ap + cb + 4 * j);
#pragma unroll
            for (int j = 0; j < 4; j++)
                bv[j] = *reinterpret_cast<const float4*>(Bp + cb + bh * 16 + 4 * j);
        }

        // ---- MMA over this chunk: 4 k8-steps, 32 HMMA each ----
        const float* As = &smf[AS_OFF(buf)];
        const float* Bs = &smf[BS_OFF(buf)];
#pragma unroll
        for (int s = 0; s < 4; s++) {
            const int ko = 8 * s + klane;
            uint2 afr[4][2], bfr[8];
#pragma unroll
            for (int mt = 0; mt < 4; mt++) {
                afr[mt][0] = *reinterpret_cast<const uint2*>(&As[(arow0 + mt * 16) * RS + ko]);
                afr[mt][1] = *reinterpret_cast<const uint2*>(&As[(arow0 + mt * 16 + 8) * RS + ko]);
            }
#pragma unroll
            for (int nt = 0; nt < 8; nt++)
                bfr[nt] = *reinterpret_cast<const uint2*>(&Bs[(brow0 + nt * 8) * RS + ko]);
#pragma unroll
            for (int mt = 0; mt < 4; mt++)
#pragma unroll
                for (int nt = 0; nt < 8; nt++)
                    mma_tf32(acc[mt][nt],
                             afr[mt][0].x, afr[mt][1].x, afr[mt][0].y, afr[mt][1].y,
                             bfr[nt].x, bfr[nt].y);
        }

        if (kt + 1 < NCHUNK) {
            const int nb = buf ^ 1;
            const int arot = (arow + 2 * (arow >> 3)) & 7;
            const int brot = brow & 3;
#pragma unroll
            for (int t = 0; t < 8; t++) {
                int j = (t + arot) & 7;
                float4 a = av[j];
                ssa = fmaf(a.x, a.x, ssa); ssa = fmaf(a.y, a.y, ssa);
                ssa = fmaf(a.z, a.z, ssa); ssa = fmaf(a.w, a.w, ssa);
                sa += a.x + a.y + a.z + a.w;
                uint4 ua = make_uint4(f2tf32(a.x), f2tf32(a.y), f2tf32(a.z), f2tf32(a.w));
                *reinterpret_cast<uint4*>(&smf[AS_OFF(nb) + arow * RS + 4 * j]) = ua;
            }
#pragma unroll
            for (int t = 0; t < 4; t++) {
                int j = (t + brot) & 3;
                float4 v = bv[j];
                ssb = fmaf(v.x, v.x, ssb); ssb = fmaf(v.y, v.y, ssb);
                ssb = fmaf(v.z, v.z, ssb); ssb = fmaf(v.w, v.w, ssb);
                sB += v.x + v.y + v.z + v.w;
                uint4 ub = make_uint4(f2tf32(v.x), f2tf32(v.y), f2tf32(v.z), f2tf32(v.w));
                *reinterpret_cast<uint4*>(&smf[BS_OFF(nb) + brow * RS + bh * 16 + 4 * j]) = ub;
            }
            __syncthreads();
        }
    }

    // ---- norms: A is thread-local; B combines pair (tid, tid^1) ----
    ssb += __shfl_xor_sync(0xffffffffu, ssb, 1);
    sB  += __shfl_xor_sync(0xffffffffu, sB, 1);
    __syncthreads();   // last-chunk MMA reads done before norms region reuse ordering
    smf[R1_OFF + arow] = ssa + 2.0f * EPSV * sa;
    if (bh == 0)
        smf[R2_OFF + brow] = ssb - 2.0f * EPSV * sB + (float)DDIM * EPSV * EPSV;
    __syncthreads();

    // ---- epilogue: d = sqrt(max(r1 + r2 - 2*dot, 0)), float2 stores ----
    float r1v[4][2];
#pragma unroll
    for (int mt = 0; mt < 4; mt++) {
        r1v[mt][0] = smf[R1_OFF + wm * 64 + mt * 16 + g];
        r1v[mt][1] = smf[R1_OFF + wm * 64 + mt * 16 + g + 8];
    }
    float2 r2v[8];
#pragma unroll
    for (int nt = 0; nt < 8; nt++)
        r2v[nt] = *reinterpret_cast<const float2*>(&smf[R2_OFF + wn * 64 + nt * 8 + klane]);

    float* Ob = out + ((size_t)(b * LDIM + m0)) * LDIM + n0;
#pragma unroll
    for (int mt = 0; mt < 4; mt++) {
#pragma unroll
        for (int nt = 0; nt < 8; nt++) {
            const int col  = wn * 64 + nt * 8 + klane;
            const int row0 = wm * 64 + mt * 16 + g;
            float2 v0, v1;
            v0.x = fsqrt_fast(fmaxf(r1v[mt][0] + r2v[nt].x - 2.0f * acc[mt][nt][0], 0.f));
            v0.y = fsqrt_fast(fmaxf(r1v[mt][0] + r2v[nt].y - 2.0f * acc[mt][nt][1], 0.f));
            v1.x = fsqrt_fast(fmaxf(r1v[mt][1] + r2v[nt].x - 2.0f * acc[mt][nt][2], 0.f));
            v1.y = fsqrt_fast(fmaxf(r1v[mt][1] + r2v[nt].y - 2.0f * acc[mt][nt][3], 0.f));
            *reinterpret_cast<float2*>(Ob + (size_t)row0 * LDIM + col)       = v0;
            *reinterpret_cast<float2*>(Ob + (size_t)(row0 + 8) * LDIM + col) = v1;
        }
    }
}

// ---------------------------------------------------------------------------
extern "C" void kernel_launch(void* const* d_in, const int* in_sizes, int n_in,
                              void* d_out, int out_size) {
    const float* A = (const float*)d_in[0];
    const float* B = (const float*)d_in[1];
    float* out = (float*)d_out;
    (void)in_sizes; (void)n_in; (void)out_size;

    cudaFuncSetAttribute(dist_tf32_kernel,
                         cudaFuncAttributeMaxDynamicSharedMemorySize, SMEM_BYTES);
    dim3 grid(LDIM / CTN, LDIM / CTM, BATCH);
    dist_tf32_kernel<<<grid, 256, SMEM_BYTES>>>(A, B, out);
}

// round 5
// speedup vs baseline: 2.0502x; 2.0502x over previous
#include <cuda_runtime.h>
#include <math.h>
#include <stdint.h>

// Problem shape (fixed): B=512, L=512, D=256, fp32.
#define BATCH 512
#define LDIM  512
#define DDIM  256
#define EPSV  1e-6f

#define CTM 128
#define CTN 128
#define KCH 32               // K elements staged per chunk
#define NCHUNK (DDIM/KCH)    // 8
#define RS 40                // smem row stride in floats (conflict-free frag loads)

// smem (floats): As[2][128][RS] | Bs[2][128][RS] | r1[128] | r2[128]
#define TILEF (128*RS)                   // 5120
#define AS_OFF(s) ((s)*TILEF)
#define BS_OFF(s) (2*TILEF + (s)*TILEF)
#define R1_OFF   (4*TILEF)
#define R2_OFF   (4*TILEF + 128)
#define SMEM_FLOATS (4*TILEF + 256)
#define SMEM_BYTES  (SMEM_FLOATS*4)      // 82,944 B -> 2 CTAs/SM fit

__device__ __forceinline__ uint32_t smem_u32(const void* p) {
    uint32_t a;
    asm("{ .reg .u64 t; cvta.to.shared.u64 t, %1; cvt.u32.u64 %0, t; }" : "=r"(a) : "l"(p));
    return a;
}
__device__ __forceinline__ float fsqrt_fast(float x) {
    float y; asm("sqrt.approx.f32 %0, %1;" : "=f"(y) : "f"(x)); return y;
}
__device__ __forceinline__ void cp16(uint32_t saddr, const float* g) {
    asm volatile("cp.async.cg.shared.global [%0], [%1], 16;" :: "r"(saddr), "l"(g));
}
__device__ __forceinline__ void cp_commit() {
    asm volatile("cp.async.commit_group;");
}
__device__ __forceinline__ void cp_wait1() {
    asm volatile("cp.async.wait_group 1;" ::: "memory");
}
__device__ __forceinline__ void cp_wait0() {
    asm volatile("cp.async.wait_group 0;" ::: "memory");
}
__device__ __forceinline__ void mma_tf32(float* c,
                                         uint32_t a0, uint32_t a1, uint32_t a2, uint32_t a3,
                                         uint32_t b0, uint32_t b1) {
    asm volatile(
        "mma.sync.aligned.m16n8k8.row.col.f32.tf32.tf32.f32 "
        "{%0,%1,%2,%3}, {%4,%5,%6,%7}, {%8,%9}, {%0,%1,%2,%3};"
        : "+f"(c[0]), "+f"(c[1]), "+f"(c[2]), "+f"(c[3])
        : "r"(a0), "r"(a1), "r"(a2), "r"(a3), "r"(b0), "r"(b1));
}

// ---------------------------------------------------------------------------
__global__ __launch_bounds__(256, 2)
void dist_tf32_kernel(const float* __restrict__ A, const float* __restrict__ B,
                      float* __restrict__ out) {
    extern __shared__ float smf[];
    const uint32_t sbase = smem_u32(smf);

    const int tid = threadIdx.x;
    const int wid = tid >> 5, lid = tid & 31;
    const int b  = blockIdx.z;
    const int m0 = blockIdx.y * CTM;
    const int n0 = blockIdx.x * CTN;

    // ---- cp.async mapping: 4 rows per warp per step, 8 lanes cover a 128B row chunk
    const int crow = (wid << 2) + (lid >> 3);   // base row 0..31 (step adds t*32)
    const int cc   = (lid & 7) * 4;             // float col within 32-wide chunk
    const float* Ag = A + ((size_t)(b * LDIM + m0 + crow)) * DDIM + cc;
    const float* Bg = B + ((size_t)(b * LDIM + n0 + crow)) * DDIM + cc;
    const uint32_t sA = sbase + 4 * (crow * RS + cc);
    const uint32_t sB = sbase + 4 * (BS_OFF(0) - AS_OFF(0)) / 4 * 4 + 4 * (crow * RS + cc); // placeholder, fixed below

    // ---- norm mapping: 2 threads per row ----
    const int nrow = tid >> 1;
    const int h    = tid & 1;

    // ---- compute mapping: 2x4 warp grid, 64x32 warp tiles ----
    const int wm = wid >> 2;         // 0..1
    const int wn = wid & 3;          // 0..3
    const int g   = lid >> 2;        // 0..7
    const int tig = lid & 3;         // 0..3
    const int klane = 2 * tig;
    const int arow0 = wm * 64 + g;
    const int brow0 = wn * 32 + g;

    float acc[4][4][4];
#pragma unroll
    for (int mt = 0; mt < 4; mt++)
#pragma unroll
        for (int nt = 0; nt < 4; nt++)
#pragma unroll
            for (int r = 0; r < 4; r++) acc[mt][nt][r] = 0.f;

    float ssa = 0.f, sa = 0.f, ssb = 0.f, sB2 = 0.f;

    // ---- stage chunks 0 and 1 ----
#pragma unroll
    for (int s = 0; s < 2; s++) {
#pragma unroll
        for (int t = 0; t < 4; t++) {
            int r = t * 32;
            cp16(sbase + 4 * (AS_OFF(s) + (crow + r) * RS + cc), Ag + (size_t)r * DDIM + s * KCH);
            cp16(sbase + 4 * (BS_OFF(s) + (crow + r) * RS + cc), Bg + (size_t)r * DDIM + s * KCH);
        }
        cp_commit();
    }

#pragma unroll 1
    for (int kt = 0; kt < NCHUNK; kt++) {
        const int buf = kt & 1;
        if (kt == NCHUNK - 1) cp_wait0(); else cp_wait1();
        __syncthreads();

        const float* As = &smf[AS_OFF(buf)];
        const float* Bs = &smf[BS_OFF(buf)];

        // ---- norms from staged fp32 (rotation -> conflict-free) ----
#pragma unroll
        for (int t = 0; t < 4; t++) {
            int j = (t + nrow) & 3;
            float4 a = *reinterpret_cast<const float4*>(&As[nrow * RS + h * 16 + 4 * j]);
            float4 v = *reinterpret_cast<const float4*>(&Bs[nrow * RS + h * 16 + 4 * j]);
            ssa = fmaf(a.x, a.x, ssa); ssa = fmaf(a.y, a.y, ssa);
            ssa = fmaf(a.z, a.z, ssa); ssa = fmaf(a.w, a.w, ssa);
            sa += a.x + a.y + a.z + a.w;
            ssb = fmaf(v.x, v.x, ssb); ssb = fmaf(v.y, v.y, ssb);
            ssb = fmaf(v.z, v.z, ssb); ssb = fmaf(v.w, v.w, ssb);
            sB2 += v.x + v.y + v.z + v.w;
        }

        // ---- MMA over this chunk: 4 k8-steps, raw fp32 bits as tf32 (RZ) ----
#pragma unroll
        for (int s = 0; s < 4; s++) {
            const int ko = 8 * s + klane;
            uint2 afr[4][2], bfr[4];
#pragma unroll
            for (int mt = 0; mt < 4; mt++) {
                afr[mt][0] = *reinterpret_cast<const uint2*>(&As[(arow0 + mt * 16) * RS + ko]);
                afr[mt][1] = *reinterpret_cast<const uint2*>(&As[(arow0 + mt * 16 + 8) * RS + ko]);
            }
#pragma unroll
            for (int nt = 0; nt < 4; nt++)
                bfr[nt] = *reinterpret_cast<const uint2*>(&Bs[(brow0 + nt * 8) * RS + ko]);
#pragma unroll
            for (int mt = 0; mt < 4; mt++)
#pragma unroll
                for (int nt = 0; nt < 4; nt++)
                    mma_tf32(acc[mt][nt],
                             afr[mt][0].x, afr[mt][1].x, afr[mt][0].y, afr[mt][1].y,
                             bfr[nt].x, bfr[nt].y);
        }

        __syncthreads();   // all reads of buf done before restaging into it

        if (kt + 2 < NCHUNK) {
            const int nk = kt + 2;
#pragma unroll
            for (int t = 0; t < 4; t++) {
                int r = t * 32;
                cp16(sbase + 4 * (AS_OFF(buf) + (crow + r) * RS + cc), Ag + (size_t)r * DDIM + nk * KCH);
                cp16(sbase + 4 * (BS_OFF(buf) + (crow + r) * RS + cc), Bg + (size_t)r * DDIM + nk * KCH);
            }
            cp_commit();
        }
    }

    // ---- norms: combine thread pair (tid, tid^1), publish to smem ----
    ssa += __shfl_xor_sync(0xffffffffu, ssa, 1);
    sa  += __shfl_xor_sync(0xffffffffu, sa, 1);
    ssb += __shfl_xor_sync(0xffffffffu, ssb, 1);
    sB2 += __shfl_xor_sync(0xffffffffu, sB2, 1);
    if (h == 0) {
        smf[R1_OFF + nrow] = ssa + 2.0f * EPSV * sa;
        smf[R2_OFF + nrow] = ssb - 2.0f * EPSV * sB2 + (float)DDIM * EPSV * EPSV;
    }
    __syncthreads();

    // ---- epilogue: d = sqrt(max(r1 + r2 - 2*dot, 0)), float2 stores ----
    float r1v[4][2];
#pragma unroll
    for (int mt = 0; mt < 4; mt++) {
        r1v[mt][0] = smf[R1_OFF + wm * 64 + mt * 16 + g];
        r1v[mt][1] = smf[R1_OFF + wm * 64 + mt * 16 + g + 8];
    }
    float2 r2v[4];
#pragma unroll
    for (int nt = 0; nt < 4; nt++)
        r2v[nt] = *reinterpret_cast<const float2*>(&smf[R2_OFF + wn * 32 + nt * 8 + klane]);

    float* Ob = out + ((size_t)(b * LDIM + m0)) * LDIM + n0;
#pragma unroll
    for (int mt = 0; mt < 4; mt++) {
#pragma unroll
        for (int nt = 0; nt < 4; nt++) {
            const int col  = wn * 32 + nt * 8 + klane;
            const int row0 = wm * 64 + mt * 16 + g;
            float2 v0, v1;
            v0.x = fsqrt_fast(fmaxf(r1v[mt][0] + r2v[nt].x - 2.0f * acc[mt][nt][0], 0.f));
            v0.y = fsqrt_fast(fmaxf(r1v[mt][0] + r2v[nt].y - 2.0f * acc[mt][nt][1], 0.f));
            v1.x = fsqrt_fast(fmaxf(r1v[mt][1] + r2v[nt].x - 2.0f * acc[mt][nt][2], 0.f));
            v1.y = fsqrt_fast(fmaxf(r1v[mt][1] + r2v[nt].y - 2.0f * acc[mt][nt][3], 0.f));
            *reinterpret_cast<float2*>(Ob + (size_t)row0 * LDIM + col)       = v0;
            *reinterpret_cast<float2*>(Ob + (size_t)(row0 + 8) * LDIM + col) = v1;
        }
    }
    (void)sB;
}

// ---------------------------------------------------------------------------
extern "C" void kernel_launch(void* const* d_in, const int* in_sizes, int n_in,
                              void* d_out, int out_size) {
    const float* A = (const float*)d_in[0];
    const float* B = (const float*)d_in[1];
    float* out = (float*)d_out;
    (void)in_sizes; (void)n_in; (void)out_size;

    cudaFuncSetAttribute(dist_tf32_kernel,
                         cudaFuncAttributeMaxDynamicSharedMemorySize, SMEM_BYTES);
    dim3 grid(LDIM / CTN, LDIM / CTM, BATCH);
    dist_tf32_kernel<<<grid, 256, SMEM_BYTES>>>(A, B, out);
}